// round 7
// baseline (speedup 1.0000x reference)
#include <cuda_runtime.h>
#include <cstdint>
#include <math.h>

#define H    8192      // DIM_HIDDEN
#define S    4096      // DIM_SOL (steps)
#define CTX  4096      // DIM_CONTEXT
#define CSZ  8         // cluster size
#define NWW  8         // worker warps per CTA
#define WTH  256       // worker threads per CTA
#define EPT  4         // hidden elems per worker thread (256*4*8 = 8192)
#define TPB  288       // 8 worker warps + logp warp (wid 8)
#define RDEP 4         // recv ring depth

// ---------------- device scratch (static, no allocs) ----------------
__device__ float  g_Wt[(size_t)S * H];   // transposed W[:, CTX:]
__device__ float  g_a0[H];               // a0 = c + W[:, :CTX] @ context
__device__ float2 g_thr2[S];             // (t_hi, t_lo) two-float logit(u_i)

// ---------------- helpers ----------------
__device__ __forceinline__ float sigmoidf_fast(float x) {
    return __fdividef(1.0f, 1.0f + __expf(-x));
}
__device__ __forceinline__ float softplusf(float y) {
    float t = fabsf(y);
    float r = log1pf(__expf(-t));
    return (y > 0.f) ? (y + r) : r;
}
__device__ __forceinline__ unsigned cluster_rank() {
    unsigned r; asm("mov.u32 %0, %%cluster_ctarank;" : "=r"(r)); return r;
}
__device__ __forceinline__ uint32_t smem_u32(const void* p) {
    return (uint32_t)__cvta_generic_to_shared(p);
}
__device__ __forceinline__ void remote_store64(uint32_t laddr, unsigned rank, unsigned long long v) {
    uint32_t raddr;
    asm volatile("mapa.shared::cluster.u32 %0, %1, %2;" : "=r"(raddr) : "r"(laddr), "r"(rank));
    asm volatile("st.relaxed.cluster.shared::cluster.b64 [%0], %1;" :: "r"(raddr), "l"(v) : "memory");
}
__device__ __forceinline__ void cluster_barrier() {
    asm volatile("barrier.cluster.arrive.aligned;" ::: "memory");
    asm volatile("barrier.cluster.wait.aligned;"   ::: "memory");
}
// interleaved dual warp-sum: two independent 5-level SHFL chains pipelined
__device__ __forceinline__ void bfly2(float& x, float& y) {
    #pragma unroll
    for (int o = 16; o > 0; o >>= 1) {
        x += __shfl_xor_sync(0xffffffffu, x, o);
        y += __shfl_xor_sync(0xffffffffu, y, o);
    }
}
// threshold compare: s = (x > t) with t = t_hi + t_lo (x is exact fp32)
__device__ __forceinline__ bool thr_cmp(float x, float2 t) {
    return (x > t.x) || ((x == t.x) && (t.y < 0.f));
}

// ---------------- init kernel 1: a0 = c + W[:, :CTX] @ context ----------------
__global__ void gemv_kernel(const float* __restrict__ W,
                            const float* __restrict__ ctxv,
                            const float* __restrict__ c) {
    __shared__ float sred[256];
    int r = blockIdx.x;
    const float* row = W + (size_t)r * (CTX + S);
    float acc = 0.f;
    for (int k = threadIdx.x; k < CTX; k += 256)
        acc += row[k] * ctxv[k];
    sred[threadIdx.x] = acc;
    __syncthreads();
    for (int off = 128; off > 0; off >>= 1) {
        if (threadIdx.x < off) sred[threadIdx.x] += sred[threadIdx.x + off];
        __syncthreads();
    }
    if (threadIdx.x == 0) g_a0[r] = c[r] + sred[0];
}

// ---------------- init kernel 2: transpose W[:, CTX:] -> g_Wt ----------------
__global__ void transpose_kernel(const float* __restrict__ W) {
    __shared__ float tile[32][33];
    int i0 = blockIdx.x * 32;   // step index base
    int j0 = blockIdx.y * 32;   // hidden index base
    int tx = threadIdx.x;
    #pragma unroll
    for (int t = 0; t < 4; t++) {
        int ty = threadIdx.y + t * 8;
        tile[ty][tx] = W[(size_t)(j0 + ty) * (CTX + S) + CTX + i0 + tx];
    }
    __syncthreads();
    #pragma unroll
    for (int t = 0; t < 4; t++) {
        int ty = threadIdx.y + t * 8;
        g_Wt[(size_t)(i0 + ty) * H + j0 + tx] = tile[tx][ty];
    }
}

// ---------------- init kernel 3: two-float thresholds ----------------
__global__ void thr_kernel(const float* __restrict__ u) {
    int i = blockIdx.x * 256 + threadIdx.x;
    if (i < S) {
        double ud = (double)u[i];
        double t  = log(ud / (1.0 - ud));
        float hi  = (float)t;
        float lo  = (float)(t - (double)hi);
        g_thr2[i] = make_float2(hi, lo);
    }
}

// ---------------- main sequential kernel: 8-CTA cluster ----------------
// recv layout per ring slot: [0..63]   = e0 words (srcCTA*8 + warp), tag in hi32
//                            [64..127] = e1 words (same index + 64)
__global__ void __cluster_dims__(CSZ, 1, 1) __launch_bounds__(TPB, 1)
nade_kernel(const float* __restrict__ V,
            const float* __restrict__ b,
            float* __restrict__ out,
            int out_size) {
    __shared__ unsigned long long recv[RDEP][128];  // worker-pair broadcast slots
    __shared__ unsigned long long xw[S];            // x per step (tagged) — no reuse

    const unsigned rank = cluster_rank();
    const int tid  = threadIdx.x;
    const int wid  = tid >> 5;
    const int lane = tid & 31;

    for (int k = tid; k < RDEP * 128; k += TPB)
        ((unsigned long long*)recv)[k] = 0xFFFFFFFF00000000ULL;
    for (int k = tid; k < S; k += TPB)
        xw[k] = 0xFFFFFFFF00000000ULL;
    __syncthreads();
    cluster_barrier();   // everyone's recv initialized before any remote store

    volatile unsigned long long* xwv = xw;

    if (wid < NWW) {
        // ================= worker warps (also decide) =================
        const int base  = (int)rank * (WTH * EPT) + tid;   // + e*WTH
        const int slotA = (int)rank * 8 + wid;             // e0 slot index
        const bool xwriter = (rank == 0 && wid == 0 && lane == 0);

        float a[EPT], h[EPT], h1[EPT];
        // deep register prefetch: distance 4
        float wPrev[EPT], wC[EPT], wN1[EPT], wN2[EPT], wN3[EPT];
        float vC[EPT], vN1[EPT], vN2[EPT], vN3[EPT];

        #pragma unroll
        for (int e = 0; e < EPT; e++) {
            int j   = base + e * WTH;
            a[e]    = g_a0[j];
            h[e]    = sigmoidf_fast(a[e]);
            wPrev[e]= g_Wt[j];                          // W_0
            wC[e]   = g_Wt[(size_t)1 * H + j];          // W_1
            wN1[e]  = g_Wt[(size_t)2 * H + j];          // W_2
            wN2[e]  = g_Wt[(size_t)3 * H + j];          // W_3
            wN3[e]  = g_Wt[(size_t)4 * H + j];          // W_4
            vC[e]   = V[(size_t)2 * H + j];             // V_2
            vN1[e]  = V[(size_t)3 * H + j];             // V_3
            vN2[e]  = V[(size_t)4 * H + j];             // V_4
            vN3[e]  = V[(size_t)5 * H + j];             // V_5
        }

        // rolling b/threshold prefetch (used when deciding step p-2 at iter p)
        float  bc = b[0],      bn = b[1];
        float2 tc = g_thr2[0], tn = g_thr2[1];
        unsigned sprev = 0;

        // send helper: lanes 0-15 broadcast the tagged pair to all 8 CTAs
        auto send_pair = [&](int p, float e0, float e1) {
            if (lane < 16) {
                float val = (lane < 8) ? e0 : e1;
                int   slot = (lane < 8) ? slotA : (64 + slotA);
                unsigned long long pk =
                    ((unsigned long long)(unsigned)p << 32) |
                    (unsigned long long)__float_as_uint(val);
                remote_store64(smem_u32(&recv[p & (RDEP - 1)][slot]), (unsigned)(lane & 7), pk);
            }
        };

        // poll + reduce both branch sums for step q (identical in all warps/CTAs)
        auto recv_reduce = [&](int q, float& D0, float& D1) {
            const unsigned want = (unsigned)q;
            volatile unsigned long long* rv = &recv[q & (RDEP - 1)][0];
            unsigned long long A0, A1, B0, B1;
            for (;;) {
                A0 = rv[2 * lane];
                A1 = rv[2 * lane + 1];
                B0 = rv[64 + 2 * lane];
                B1 = rv[64 + 2 * lane + 1];
                if (((unsigned)(A0 >> 32) == want) & ((unsigned)(A1 >> 32) == want) &
                    ((unsigned)(B0 >> 32) == want) & ((unsigned)(B1 >> 32) == want))
                    break;
            }
            float d0 = __uint_as_float((unsigned)A0) + __uint_as_float((unsigned)A1);
            float d1 = __uint_as_float((unsigned)B0) + __uint_as_float((unsigned)B1);
            bfly2(d0, d1);
            D0 = d0; D1 = d1;
        };

        // prologue: pair(0) = V_0 . h (both branches equal); pair(1) over s_0
        {
            float e0 = 0.f, dummy = 0.f;
            #pragma unroll
            for (int e = 0; e < EPT; e++)
                e0 = fmaf(V[base + e * WTH], h[e], e0);
            bfly2(e0, dummy);
            send_pair(0, e0, e0);
        }
        {
            float e0 = 0.f, e1 = 0.f;
            #pragma unroll
            for (int e = 0; e < EPT; e++) {
                h1[e] = sigmoidf_fast(a[e] + wPrev[e]);   // sigma(a0 + W_0)
                float v1 = V[(size_t)1 * H + base + e * WTH];
                e0 = fmaf(v1, h[e],  e0);
                e1 = fmaf(v1, h1[e], e1);
            }
            bfly2(e0, e1);
            send_pair(1, e0, e1);
        }

        #pragma unroll 4
        for (int p = 2; p < S; p++) {
            // far-ahead prefetches (fly during the recv wait)
            int pw = (p + 3 < S) ? p + 3 : S - 1;   // W row used at iter p+4
            int pv = (p + 4 < S) ? p + 4 : S - 1;   // V row used at iter p+4
            float wf[EPT], vf[EPT];
            #pragma unroll
            for (int e = 0; e < EPT; e++) {
                wf[e] = g_Wt[(size_t)pw * H + base + e * WTH];
                vf[e] = V[(size_t)pv * H + base + e * WTH];
            }
            float  bf = b[p];          // for deciding step p at iter p+2
            float2 tf = g_thr2[p];

            // ---- decide step p-2 locally ----
            float D0, D1;
            recv_reduce(p - 2, D0, D1);
            float x = bc + (sprev ? D1 : D0);
            bool  s = thr_cmp(x, tc);
            sprev = (unsigned)s;
            if (xwriter)
                xwv[p - 2] = ((unsigned long long)(unsigned)(p - 2) << 32) |
                             (unsigned long long)__float_as_uint(x);

            // ---- commit, speculate, dot ----
            float sm = (float)s;
            float e0 = 0.f, e1 = 0.f;
            #pragma unroll
            for (int e = 0; e < EPT; e++) {
                a[e] = fmaf(sm, wPrev[e], a[e]);
                h[e] = s ? h1[e] : h[e];
                h1[e] = sigmoidf_fast(a[e] + wC[e]);   // branch s_{p-1}=1
                e0 = fmaf(vC[e], h[e],  e0);
                e1 = fmaf(vC[e], h1[e], e1);
            }
            bfly2(e0, e1);
            send_pair(p, e0, e1);

            // rotate buffers
            #pragma unroll
            for (int e = 0; e < EPT; e++) {
                wPrev[e] = wC[e]; wC[e] = wN1[e]; wN1[e] = wN2[e]; wN2[e] = wN3[e]; wN3[e] = wf[e];
                vC[e] = vN1[e]; vN1[e] = vN2[e]; vN2[e] = vN3[e]; vN3[e] = vf[e];
            }
            bc = bn; bn = bf; tc = tn; tn = tf;
        }

        // ---- tail: decide steps S-2 and S-1 (x needed for out[]) ----
        if (rank == 0 && wid == 0) {
            #pragma unroll
            for (int q = S - 2; q < S; q++) {
                float D0, D1;
                recv_reduce(q, D0, D1);
                float x = bc + (sprev ? D1 : D0);
                bool  s = thr_cmp(x, tc);
                sprev = (unsigned)s;
                if (lane == 0)
                    xwv[q] = ((unsigned long long)(unsigned)q << 32) |
                             (unsigned long long)__float_as_uint(x);
                bc = bn; tc = tn;
            }
        }
    } else {
        // ================= logp/output warp (rank 0, lane 0 only) =================
        if (rank == 0 && lane == 0) {
            float2 tc = g_thr2[0], tn = g_thr2[1];
            double lp = 0.0;
            for (int i = 0; i < S; i++) {
                unsigned long long xv;
                do { xv = xwv[i]; } while ((unsigned)(xv >> 32) != (unsigned)i);
                float x = __uint_as_float((unsigned)xv);
                bool  s = thr_cmp(x, tc);
                out[i] = s ? 1.0f : 0.0f;
                if (i < S - 2)
                    lp -= (double)(s ? softplusf(-x) : softplusf(x));
                int ip = (i + 2 < S) ? i + 2 : S - 1;
                float2 tf = g_thr2[ip];
                tc = tn; tn = tf;
            }
            out[S] = (float)lp;
            for (int k = S + 1; k < out_size; k++) out[k] = 0.f;
        }
    }

    cluster_barrier();   // no CTA exits while peers may still store to its smem
}

// ---------------- launch ----------------
extern "C" void kernel_launch(void* const* d_in, const int* in_sizes, int n_in,
                              void* d_out, int out_size) {
    const float* ctxv = nullptr;
    const float* u    = nullptr;
    const float* W    = nullptr;
    const float* V    = nullptr;
    const float* b    = nullptr;
    const float* c    = nullptr;

    const int szW = (CTX + S) * H;   // 67108864
    const int szV = S * H;           // 33554432
    int n4seen = 0;
    for (int idx = 0; idx < n_in; idx++) {
        int sz = in_sizes[idx];
        const float* p = (const float*)d_in[idx];
        if (sz == szW)       W = p;
        else if (sz == szV)  V = p;
        else if (sz == H)    c = p;
        else if (sz == S) {
            if      (n4seen == 0) ctxv = p;
            else if (n4seen == 1) u    = p;
            else                  b    = p;
            n4seen++;
        }
    }
    if (!ctxv) ctxv = (const float*)d_in[0];
    if (!u)    u    = (const float*)d_in[1];
    if (!W)    W    = (const float*)d_in[2];
    if (!V)    V    = (const float*)d_in[3];
    if (!b)    b    = (const float*)d_in[4];
    if (!c)    c    = (const float*)d_in[5];

    float* out = (float*)d_out;

    gemv_kernel<<<H, 256>>>(W, ctxv, c);
    transpose_kernel<<<dim3(S / 32, H / 32), dim3(32, 8)>>>(W);
    thr_kernel<<<(S + 255) / 256, 256>>>(u);
    nade_kernel<<<CSZ, TPB>>>(V, b, out, out_size);
}